// round 10
// baseline (speedup 1.0000x reference)
#include <cuda_runtime.h>
#include <cstddef>

// Problem shape (fixed by the dataset): B=8, C=256, H=W=64, N=H*W=4096
static constexpr int BB = 8;
static constexpr int CC = 256;
static constexpr int NN = 4096;
static constexpr long CN = (long)CC * NN;        // 1,048,576
static constexpr long NNN = (long)NN * NN;       // 16,777,216

// Scratch (allocation-free rule: __device__ globals)
__device__ float g_wt[3][CC * CC];               // W^T for q,k,v:  [c][d]
__device__ float g_q[BB * CC * NN];              // q[b][c][n]
__device__ float g_k[BB * CC * NN];              // k[b][c][n]
__device__ float g_v[BB * CC * NN];              // v[b][c][n]
__device__ float g_s[(size_t)BB * NN * NN];      // s[b][m][n] = qk^T (scores, then probs)

// ---------------------------------------------------------------------------
// Transpose the three 256x256 weight matrices: g_wt[w][c][d] = W[d][c]
// ---------------------------------------------------------------------------
__global__ void transpose_w(const float* __restrict__ Wq,
                            const float* __restrict__ Wk,
                            const float* __restrict__ Wv) {
    int idx = blockIdx.x * blockDim.x + threadIdx.x;   // 0 .. 65535
    int w = blockIdx.y;                                 // 0,1,2
    const float* src = (w == 0) ? Wq : (w == 1) ? Wk : Wv;
    int d = idx >> 8;          // row of W
    int c = idx & 255;         // col of W
    g_wt[w][c * CC + d] = src[d * CC + c];
}

// ---------------------------------------------------------------------------
// TN GEMM (double-buffered):
//   C[b][m][n] = alpha * sum_k A[b][k][m] * B[b][k][n]  (+ bias[m])
// A is K-major with M contiguous; B is K-major with N contiguous.
// BM=BN=128, BK=8, 256 threads, 8x8 per thread. All dims divide tiles exactly.
// ---------------------------------------------------------------------------
__global__ __launch_bounds__(256)
void gemm_tn(const float* __restrict__ A, long strideA,
             const float* __restrict__ B, long strideB,
             float* __restrict__ C, long strideC,
             const float* __restrict__ bias,
             int M, int N, int K, float alpha) {
    __shared__ float As[2][8][132];   // pad 132: conflict-free LDS
    __shared__ float Bs[2][8][132];

    const int b  = blockIdx.z;
    const int m0 = blockIdx.y * 128;
    const int n0 = blockIdx.x * 128;
    A += (size_t)b * strideA;
    B += (size_t)b * strideB;
    C += (size_t)b * strideC;

    const int tid = threadIdx.x;
    const int lr  = tid >> 5;          // 0..7   (k row within tile)
    const int lc  = (tid & 31) * 4;    // 0..124 (col, float4)
    const int tm  = tid >> 4;          // 0..15
    const int tn  = tid & 15;          // 0..15

    const float* pA = &A[(size_t)lr * M + m0 + lc];
    const float* pB = &B[(size_t)lr * N + n0 + lc];

    float acc[8][8] = {};

    // Prologue: fill buffer 0 with k0 = 0
    *(float4*)&As[0][lr][lc] = *(const float4*)pA;
    *(float4*)&Bs[0][lr][lc] = *(const float4*)pB;
    __syncthreads();

    int buf = 0;
    for (int k0 = 0; k0 < K; k0 += 8) {
        // Issue next tile's global loads early; store into the other buffer.
        if (k0 + 8 < K) {
            float4 na = *(const float4*)&pA[(size_t)(k0 + 8) * M];
            float4 nb = *(const float4*)&pB[(size_t)(k0 + 8) * N];
            *(float4*)&As[buf ^ 1][lr][lc] = na;
            *(float4*)&Bs[buf ^ 1][lr][lc] = nb;
        }
        #pragma unroll
        for (int kk = 0; kk < 8; kk++) {
            float a[8], bb[8];
            *(float4*)&a[0]  = *(float4*)&As[buf][kk][tm * 8];
            *(float4*)&a[4]  = *(float4*)&As[buf][kk][tm * 8 + 4];
            *(float4*)&bb[0] = *(float4*)&Bs[buf][kk][tn * 8];
            *(float4*)&bb[4] = *(float4*)&Bs[buf][kk][tn * 8 + 4];
            #pragma unroll
            for (int i = 0; i < 8; i++)
                #pragma unroll
                for (int j = 0; j < 8; j++)
                    acc[i][j] += a[i] * bb[j];
        }
        __syncthreads();
        buf ^= 1;
    }

    #pragma unroll
    for (int i = 0; i < 8; i++) {
        int m = m0 + tm * 8 + i;
        float bv = bias ? bias[m] : 0.0f;
        float4 o0, o1;
        o0.x = alpha * acc[i][0] + bv; o0.y = alpha * acc[i][1] + bv;
        o0.z = alpha * acc[i][2] + bv; o0.w = alpha * acc[i][3] + bv;
        o1.x = alpha * acc[i][4] + bv; o1.y = alpha * acc[i][5] + bv;
        o1.z = alpha * acc[i][6] + bv; o1.w = alpha * acc[i][7] + bv;
        *(float4*)&C[(size_t)m * N + n0 + tn * 8]     = o0;
        *(float4*)&C[(size_t)m * N + n0 + tn * 8 + 4] = o1;
    }
}

// ---------------------------------------------------------------------------
// Row softmax over the last axis (n) of s[b][m][:], 4096 elements per row.
// One block (256 threads) per row; values kept in registers (16 per thread).
// ---------------------------------------------------------------------------
__global__ __launch_bounds__(256)
void softmax_rows(float* __restrict__ S) {
    float* p = S + (size_t)blockIdx.x * NN;
    const int tid = threadIdx.x;
    __shared__ float shm[8];
    __shared__ float shs[8];

    float v[16];
    float mx = -1e30f;
    #pragma unroll
    for (int i = 0; i < 16; i++) {
        v[i] = p[tid + i * 256];
        mx = fmaxf(mx, v[i]);
    }
    #pragma unroll
    for (int o = 16; o; o >>= 1) mx = fmaxf(mx, __shfl_xor_sync(0xffffffffu, mx, o));
    if ((tid & 31) == 0) shm[tid >> 5] = mx;
    __syncthreads();
    mx = shm[0];
    #pragma unroll
    for (int i = 1; i < 8; i++) mx = fmaxf(mx, shm[i]);

    float sum = 0.0f;
    #pragma unroll
    for (int i = 0; i < 16; i++) {
        v[i] = __expf(v[i] - mx);
        sum += v[i];
    }
    #pragma unroll
    for (int o = 16; o; o >>= 1) sum += __shfl_xor_sync(0xffffffffu, sum, o);
    if ((tid & 31) == 0) shs[tid >> 5] = sum;
    __syncthreads();
    sum = 0.0f;
    #pragma unroll
    for (int i = 0; i < 8; i++) sum += shs[i];

    float inv = 1.0f / sum;
    #pragma unroll
    for (int i = 0; i < 16; i++) p[tid + i * 256] = v[i] * inv;
}

// ---------------------------------------------------------------------------
// NT GEMM + epilogue (double-buffered):
//   o[b][i][j] = sum_t A[b][i][t] * B[b][j][t]
//   out[b][i][j] = gamma * o + X[b][i][j]
// A = v[c][n] (Mo=256, K=4096), B = probs[m][n] (No=4096, K=4096).
// ---------------------------------------------------------------------------
__global__ __launch_bounds__(256)
void gemm_nt_out(const float* __restrict__ A, long strideA,
                 const float* __restrict__ B, long strideB,
                 const float* __restrict__ X,
                 const float* __restrict__ gamma,
                 float* __restrict__ Out,
                 int Mo, int No, int K) {
    __shared__ float As[2][8][132];
    __shared__ float Bs[2][8][132];

    const int b  = blockIdx.z;
    const int i0 = blockIdx.y * 128;
    const int j0 = blockIdx.x * 128;
    A += (size_t)b * strideA;
    B += (size_t)b * strideB;
    const size_t outoff = (size_t)b * Mo * No;

    const int tid = threadIdx.x;
    const int row = tid >> 1;          // 0..127
    const int q4  = (tid & 1) * 4;     // 0 or 4
    const int tm  = tid >> 4;
    const int tn  = tid & 15;

    const float* pA = &A[(size_t)(i0 + row) * K + q4];
    const float* pB = &B[(size_t)(j0 + row) * K + q4];

    float acc[8][8] = {};

    // Prologue: fill buffer 0 with k0 = 0
    {
        float4 av = *(const float4*)pA;
        float4 bv = *(const float4*)pB;
        As[0][q4 + 0][row] = av.x; As[0][q4 + 1][row] = av.y;
        As[0][q4 + 2][row] = av.z; As[0][q4 + 3][row] = av.w;
        Bs[0][q4 + 0][row] = bv.x; Bs[0][q4 + 1][row] = bv.y;
        Bs[0][q4 + 2][row] = bv.z; Bs[0][q4 + 3][row] = bv.w;
    }
    __syncthreads();

    int buf = 0;
    for (int k0 = 0; k0 < K; k0 += 8) {
        if (k0 + 8 < K) {
            float4 av = *(const float4*)&pA[k0 + 8];
            float4 bv = *(const float4*)&pB[k0 + 8];
            As[buf ^ 1][q4 + 0][row] = av.x; As[buf ^ 1][q4 + 1][row] = av.y;
            As[buf ^ 1][q4 + 2][row] = av.z; As[buf ^ 1][q4 + 3][row] = av.w;
            Bs[buf ^ 1][q4 + 0][row] = bv.x; Bs[buf ^ 1][q4 + 1][row] = bv.y;
            Bs[buf ^ 1][q4 + 2][row] = bv.z; Bs[buf ^ 1][q4 + 3][row] = bv.w;
        }
        #pragma unroll
        for (int kk = 0; kk < 8; kk++) {
            float a[8], bb[8];
            *(float4*)&a[0]  = *(float4*)&As[buf][kk][tm * 8];
            *(float4*)&a[4]  = *(float4*)&As[buf][kk][tm * 8 + 4];
            *(float4*)&bb[0] = *(float4*)&Bs[buf][kk][tn * 8];
            *(float4*)&bb[4] = *(float4*)&Bs[buf][kk][tn * 8 + 4];
            #pragma unroll
            for (int i = 0; i < 8; i++)
                #pragma unroll
                for (int j = 0; j < 8; j++)
                    acc[i][j] += a[i] * bb[j];
        }
        __syncthreads();
        buf ^= 1;
    }

    const float g = *gamma;
    #pragma unroll
    for (int i = 0; i < 8; i++) {
        size_t base = outoff + (size_t)(i0 + tm * 8 + i) * No + j0 + tn * 8;
        float4 x0 = *(const float4*)&X[base];
        float4 x1 = *(const float4*)&X[base + 4];
        float4 o0, o1;
        o0.x = g * acc[i][0] + x0.x; o0.y = g * acc[i][1] + x0.y;
        o0.z = g * acc[i][2] + x0.z; o0.w = g * acc[i][3] + x0.w;
        o1.x = g * acc[i][4] + x1.x; o1.y = g * acc[i][5] + x1.y;
        o1.z = g * acc[i][6] + x1.z; o1.w = g * acc[i][7] + x1.w;
        *(float4*)&Out[base]     = o0;
        *(float4*)&Out[base + 4] = o1;
    }
}

// ---------------------------------------------------------------------------
// Launch
// ---------------------------------------------------------------------------
extern "C" void kernel_launch(void* const* d_in, const int* in_sizes, int n_in,
                              void* d_out, int out_size) {
    const float* x     = (const float*)d_in[0];
    const float* Wq    = (const float*)d_in[1];
    const float* bq    = (const float*)d_in[2];
    const float* Wk    = (const float*)d_in[3];
    const float* bk    = (const float*)d_in[4];
    const float* Wv    = (const float*)d_in[5];
    const float* bv    = (const float*)d_in[6];
    const float* gamma = (const float*)d_in[7];
    float* out = (float*)d_out;

    float *wt, *q, *k, *v, *s;
    cudaGetSymbolAddress((void**)&wt, g_wt);
    cudaGetSymbolAddress((void**)&q,  g_q);
    cudaGetSymbolAddress((void**)&k,  g_k);
    cudaGetSymbolAddress((void**)&v,  g_v);
    cudaGetSymbolAddress((void**)&s,  g_s);

    // 1) W transposes
    transpose_w<<<dim3((CC * CC) / 256, 3), 256>>>(Wq, Wk, Wv);

    // 2) q,k,v = W^T-as-TN GEMM over f = x  (M=256, N=4096, K=256)
    dim3 gProj(NN / 128, CC / 128, BB);
    gemm_tn<<<gProj, 256>>>(wt + 0 * CC * CC, 0, x, CN, q, CN, bq, CC, NN, CC, 1.0f);
    gemm_tn<<<gProj, 256>>>(wt + 1 * CC * CC, 0, x, CN, k, CN, bk, CC, NN, CC, 1.0f);
    gemm_tn<<<gProj, 256>>>(wt + 2 * CC * CC, 0, x, CN, v, CN, bv, CC, NN, CC, 1.0f);

    // 3) s[b][m][n] = (1/W) * sum_c k[b][c][m] * q[b][c][n]   (M=N=4096, K=256)
    dim3 gScore(NN / 128, NN / 128, BB);
    gemm_tn<<<gScore, 256>>>(k, CN, q, CN, s, NNN, nullptr, NN, NN, CC, 1.0f / 64.0f);

    // 4) softmax over n (contiguous rows of s)
    softmax_rows<<<BB * NN, 256>>>(s);

    // 5) out[b][c][m] = gamma * sum_n v[b][c][n] * p[b][m][n] + x[b][c][m]
    dim3 gOut(NN / 128, CC / 128, BB);
    gemm_nt_out<<<gOut, 256>>>(v, CN, s, NNN, x, gamma, out, CC, NN, NN);
}

// round 15
// speedup vs baseline: 3.8089x; 3.8089x over previous
#include <cuda_runtime.h>
#include <cuda_bf16.h>
#include <cstddef>
#include <cstdint>

// Problem shape (fixed): B=8, C=256, H=W=64, N=H*W=4096
static constexpr int BB = 8;
static constexpr int CC = 256;
static constexpr int NN = 4096;
static constexpr long CN  = (long)CC * NN;       // 1,048,576
static constexpr long NNN = (long)NN * NN;       // 16,777,216

// Scratch (__device__ globals; allocation-free rule)
__device__ __align__(128) float          g_wt[3][CC * CC];             // W^T  [c][d]
__device__ __align__(128) __nv_bfloat16  g_qT[(size_t)BB * NN * CC];   // qT[b][token][c]
__device__ __align__(128) __nv_bfloat16  g_kT[(size_t)BB * NN * CC];   // kT[b][token][c]
__device__ __align__(128) __nv_bfloat16  g_v [(size_t)BB * CC * NN];   // v[b][c][n]
__device__ __align__(128) float          g_s [(size_t)BB * NN * NN];   // scores s[b][m][n]
__device__ __align__(128) __nv_bfloat16  g_p [(size_t)BB * NN * NN];   // probs  P[b][m][n]

// ---------------------------------------------------------------------------
// Portable (non-'a') tensor-core helpers: ldmatrix + mma.sync bf16 (sm_80+)
// ---------------------------------------------------------------------------
__device__ __forceinline__ unsigned smem_u32(const void* p) {
    unsigned a;
    asm("{ .reg .u64 t; cvta.to.shared.u64 t, %1; cvt.u32.u64 %0, t; }"
        : "=r"(a) : "l"(p));
    return a;
}
__device__ __forceinline__ void ldsm4(unsigned* r, unsigned addr) {
    asm volatile("ldmatrix.sync.aligned.m8n8.x4.shared.b16 {%0,%1,%2,%3}, [%4];"
                 : "=r"(r[0]), "=r"(r[1]), "=r"(r[2]), "=r"(r[3]) : "r"(addr));
}
__device__ __forceinline__ void mma16816(float* d, const unsigned* a, const unsigned* b) {
    asm volatile("mma.sync.aligned.m16n8k16.row.col.f32.bf16.bf16.f32 "
                 "{%0,%1,%2,%3}, {%4,%5,%6,%7}, {%8,%9}, {%0,%1,%2,%3};"
                 : "+f"(d[0]), "+f"(d[1]), "+f"(d[2]), "+f"(d[3])
                 : "r"(a[0]), "r"(a[1]), "r"(a[2]), "r"(a[3]),
                   "r"(b[0]), "r"(b[1]));
}

// ---------------------------------------------------------------------------
// HMMA NT mainloop over a 128x128 C-tile:
//   acc[mt][nt][] += A[128 rows, K] · B[128 rows, K]^T   (bf16, fp32 accum)
// A,B row-major, K-contiguous. SMEM tiles 128 rows x 64 k (128B/row, SW128 XOR).
// 256 threads, 8 warps as 2(m) x 4(n); warp tile 64x32; 16 m16n8k16 per k-step.
// Register-prefetch double buffering over single-buffered SMEM.
// ---------------------------------------------------------------------------
__device__ __forceinline__ void hmma_mainloop(
    const __nv_bfloat16* __restrict__ A, long lda,
    const __nv_bfloat16* __restrict__ B, long ldb, int K,
    unsigned char* smA, unsigned char* smB,
    float acc[4][4][4])
{
    const int tid  = threadIdx.x;
    const int lane = tid & 31;
    const int wid  = tid >> 5;
    const int wm   = wid & 1;        // 0..1  (m half)
    const int wn   = wid >> 1;       // 0..3  (n quarter)
    const unsigned sA = smem_u32(smA);
    const unsigned sB = smem_u32(smB);

    const int frow = tid >> 3;       // fill row base (rows frow + i*32)
    const int fseg = tid & 7;        // 16B segment within 128B row

    uint4 ra[4], rb[4];
    #pragma unroll
    for (int i = 0; i < 4; i++) {
        int row = frow + i * 32;
        ra[i] = *(const uint4*)(A + (size_t)row * lda + fseg * 8);
        rb[i] = *(const uint4*)(B + (size_t)row * ldb + fseg * 8);
    }

    for (int k0 = 0; k0 < K; k0 += 64) {
        // Store the prefetched tile (SW128 XOR swizzle, 16B granularity)
        #pragma unroll
        for (int i = 0; i < 4; i++) {
            int row = frow + i * 32;
            unsigned off = row * 128 + ((fseg ^ (row & 7)) << 4);
            *(uint4*)(smA + off) = ra[i];
            *(uint4*)(smB + off) = rb[i];
        }
        __syncthreads();

        // Issue next tile's global loads early (hidden behind the MMA work)
        if (k0 + 64 < K) {
            #pragma unroll
            for (int i = 0; i < 4; i++) {
                int row = frow + i * 32;
                ra[i] = *(const uint4*)(A + (size_t)row * lda + k0 + 64 + fseg * 8);
                rb[i] = *(const uint4*)(B + (size_t)row * ldb + k0 + 64 + fseg * 8);
            }
        }

        const int ah = lane >> 4;    // k-half select for ldmatrix groups
        #pragma unroll
        for (int ks = 0; ks < 4; ks++) {
            unsigned aF[4][4], bF[4][2];
            #pragma unroll
            for (int mt = 0; mt < 4; mt++) {
                int row   = wm * 64 + mt * 16 + (lane & 15);
                int chunk = ks * 2 + ah;
                ldsm4(aF[mt], sA + row * 128 + ((chunk ^ (row & 7)) << 4));
            }
            #pragma unroll
            for (int nt2 = 0; nt2 < 2; nt2++) {
                unsigned r[4];
                int row   = wn * 32 + nt2 * 16 + (lane & 7) + ((lane >> 3) & 1) * 8;
                int chunk = ks * 2 + ah;
                ldsm4(r, sB + row * 128 + ((chunk ^ (row & 7)) << 4));
                bF[nt2 * 2 + 0][0] = r[0]; bF[nt2 * 2 + 0][1] = r[2];
                bF[nt2 * 2 + 1][0] = r[1]; bF[nt2 * 2 + 1][1] = r[3];
            }
            #pragma unroll
            for (int mt = 0; mt < 4; mt++)
                #pragma unroll
                for (int nt = 0; nt < 4; nt++)
                    mma16816(acc[mt][nt], aF[mt], bF[nt]);
        }
        __syncthreads();
    }
}

// ---------------------------------------------------------------------------
// Transpose the three 256x256 weight matrices: g_wt[w][c][d] = W[d][c]
// ---------------------------------------------------------------------------
__global__ void transpose_w(const float* __restrict__ Wq,
                            const float* __restrict__ Wk,
                            const float* __restrict__ Wv) {
    int idx = blockIdx.x * blockDim.x + threadIdx.x;
    int w = blockIdx.y;
    const float* src = (w == 0) ? Wq : (w == 1) ? Wk : Wv;
    int d = idx >> 8;
    int c = idx & 255;
    g_wt[w][c * CC + d] = src[d * CC + c];
}

// ---------------------------------------------------------------------------
// TN GEMM (fp32 compute, double-buffered SMEM, bf16 output):
//   C[b][m][n] = sum_k A[b][k][m]*B[b][k][n] + biasM[m] + biasN[n]
// ---------------------------------------------------------------------------
__global__ __launch_bounds__(256)
void gemm_tn_bf16(const float* __restrict__ A, long strideA,
                  const float* __restrict__ B, long strideB,
                  __nv_bfloat16* __restrict__ C, long strideC,
                  const float* __restrict__ biasM,
                  const float* __restrict__ biasN,
                  int M, int N, int K) {
    __shared__ float As[2][8][132];
    __shared__ float Bs[2][8][132];

    const int b  = blockIdx.z;
    const int m0 = blockIdx.y * 128;
    const int n0 = blockIdx.x * 128;
    A += (size_t)b * strideA;
    B += (size_t)b * strideB;
    C += (size_t)b * strideC;

    const int tid = threadIdx.x;
    const int lr  = tid >> 5;
    const int lc  = (tid & 31) * 4;
    const int tm  = tid >> 4;
    const int tn  = tid & 15;

    const float* pA = &A[(size_t)lr * M + m0 + lc];
    const float* pB = &B[(size_t)lr * N + n0 + lc];

    float acc[8][8] = {};

    *(float4*)&As[0][lr][lc] = *(const float4*)pA;
    *(float4*)&Bs[0][lr][lc] = *(const float4*)pB;
    __syncthreads();

    int buf = 0;
    for (int k0 = 0; k0 < K; k0 += 8) {
        if (k0 + 8 < K) {
            float4 na = *(const float4*)&pA[(size_t)(k0 + 8) * M];
            float4 nb = *(const float4*)&pB[(size_t)(k0 + 8) * N];
            *(float4*)&As[buf ^ 1][lr][lc] = na;
            *(float4*)&Bs[buf ^ 1][lr][lc] = nb;
        }
        #pragma unroll
        for (int kk = 0; kk < 8; kk++) {
            float a[8], bb[8];
            *(float4*)&a[0]  = *(float4*)&As[buf][kk][tm * 8];
            *(float4*)&a[4]  = *(float4*)&As[buf][kk][tm * 8 + 4];
            *(float4*)&bb[0] = *(float4*)&Bs[buf][kk][tn * 8];
            *(float4*)&bb[4] = *(float4*)&Bs[buf][kk][tn * 8 + 4];
            #pragma unroll
            for (int i = 0; i < 8; i++)
                #pragma unroll
                for (int j = 0; j < 8; j++)
                    acc[i][j] += a[i] * bb[j];
        }
        __syncthreads();
        buf ^= 1;
    }

    #pragma unroll
    for (int i = 0; i < 8; i++) {
        int m = m0 + tm * 8 + i;
        float bm = biasM ? biasM[m] : 0.0f;
        unsigned short u[8];
        #pragma unroll
        for (int j = 0; j < 8; j++) {
            int n = n0 + tn * 8 + j;
            float bn = biasN ? biasN[n] : 0.0f;
            __nv_bfloat16 t = __float2bfloat16_rn(acc[i][j] + bm + bn);
            u[j] = *reinterpret_cast<unsigned short*>(&t);
        }
        *(uint4*)&C[(size_t)m * N + n0 + tn * 8] = *(uint4*)u;
    }
}

// ---------------------------------------------------------------------------
// HMMA score GEMM: s[b][m][n] = (1/64) * sum_c kT[b][m][c] * qT[b][n][c]
// ---------------------------------------------------------------------------
__global__ __launch_bounds__(256)
void score_hmma(const __nv_bfloat16* __restrict__ kT,
                const __nv_bfloat16* __restrict__ qT,
                float* __restrict__ S) {
    __shared__ __align__(1024) unsigned char smA[16384];
    __shared__ __align__(1024) unsigned char smB[16384];

    const int b  = blockIdx.z;
    const int m0 = blockIdx.y * 128;
    const int n0 = blockIdx.x * 128;
    const int lane = threadIdx.x & 31;
    const int wid  = threadIdx.x >> 5;
    const int wm = wid & 1, wn = wid >> 1;

    float acc[4][4][4] = {};
    hmma_mainloop(kT + ((size_t)b * NN + m0) * CC, CC,
                  qT + ((size_t)b * NN + n0) * CC, CC,
                  CC, smA, smB, acc);

    const float sc = 0.015625f;   // 1/64
    float* Sb = S + (size_t)b * NNN;
    #pragma unroll
    for (int mt = 0; mt < 4; mt++) {
        int r = m0 + wm * 64 + mt * 16 + (lane >> 2);
        #pragma unroll
        for (int nt = 0; nt < 4; nt++) {
            int c = n0 + wn * 32 + nt * 8 + (lane & 3) * 2;
            float2 v0 = { acc[mt][nt][0] * sc, acc[mt][nt][1] * sc };
            float2 v1 = { acc[mt][nt][2] * sc, acc[mt][nt][3] * sc };
            *(float2*)&Sb[(size_t)r * NN + c]       = v0;
            *(float2*)&Sb[(size_t)(r + 8) * NN + c] = v1;
        }
    }
}

// ---------------------------------------------------------------------------
// Row softmax (over contiguous n) of s[b][m][:], writes bf16 probs P.
// ---------------------------------------------------------------------------
__global__ __launch_bounds__(256)
void softmax_rows(const float* __restrict__ S, __nv_bfloat16* __restrict__ P) {
    const float* p = S + (size_t)blockIdx.x * NN;
    __nv_bfloat16* q = P + (size_t)blockIdx.x * NN;
    const int tid = threadIdx.x;
    __shared__ float shm[8];
    __shared__ float shs[8];

    float v[16];
    float mx = -1e30f;
    #pragma unroll
    for (int i = 0; i < 16; i++) {
        v[i] = p[tid + i * 256];
        mx = fmaxf(mx, v[i]);
    }
    #pragma unroll
    for (int o = 16; o; o >>= 1) mx = fmaxf(mx, __shfl_xor_sync(0xffffffffu, mx, o));
    if ((tid & 31) == 0) shm[tid >> 5] = mx;
    __syncthreads();
    mx = shm[0];
    #pragma unroll
    for (int i = 1; i < 8; i++) mx = fmaxf(mx, shm[i]);

    float sum = 0.0f;
    #pragma unroll
    for (int i = 0; i < 16; i++) {
        v[i] = __expf(v[i] - mx);
        sum += v[i];
    }
    #pragma unroll
    for (int o = 16; o; o >>= 1) sum += __shfl_xor_sync(0xffffffffu, sum, o);
    if ((tid & 31) == 0) shs[tid >> 5] = sum;
    __syncthreads();
    sum = 0.0f;
    #pragma unroll
    for (int i = 0; i < 8; i++) sum += shs[i];

    float inv = 1.0f / sum;
    #pragma unroll
    for (int i = 0; i < 16; i++) q[tid + i * 256] = __float2bfloat16_rn(v[i] * inv);
}

// ---------------------------------------------------------------------------
// HMMA output GEMM + epilogue:
//   out[b][c][m] = gamma * sum_n v[b][c][n] * P[b][m][n] + x[b][c][m]
// ---------------------------------------------------------------------------
__global__ __launch_bounds__(256)
void out_hmma(const __nv_bfloat16* __restrict__ V,
              const __nv_bfloat16* __restrict__ P,
              const float* __restrict__ X,
              const float* __restrict__ gamma,
              float* __restrict__ Out) {
    __shared__ __align__(1024) unsigned char smA[16384];
    __shared__ __align__(1024) unsigned char smB[16384];

    const int b  = blockIdx.z;
    const int c0 = blockIdx.y * 128;
    const int m0 = blockIdx.x * 128;
    const int lane = threadIdx.x & 31;
    const int wid  = threadIdx.x >> 5;
    const int wm = wid & 1, wn = wid >> 1;

    float acc[4][4][4] = {};
    hmma_mainloop(V + ((size_t)b * CC + c0) * NN, NN,
                  P + ((size_t)b * NN + m0) * NN, NN,
                  NN, smA, smB, acc);

    const float g = *gamma;
    #pragma unroll
    for (int mt = 0; mt < 4; mt++) {
        int cr = c0 + wm * 64 + mt * 16 + (lane >> 2);
        #pragma unroll
        for (int nt = 0; nt < 4; nt++) {
            int mc = m0 + wn * 32 + nt * 8 + (lane & 3) * 2;
            size_t base0 = ((size_t)b * CC + cr) * NN + mc;
            size_t base1 = ((size_t)b * CC + cr + 8) * NN + mc;
            float2 x0 = *(const float2*)&X[base0];
            float2 x1 = *(const float2*)&X[base1];
            float2 o0 = { g * acc[mt][nt][0] + x0.x, g * acc[mt][nt][1] + x0.y };
            float2 o1 = { g * acc[mt][nt][2] + x1.x, g * acc[mt][nt][3] + x1.y };
            *(float2*)&Out[base0] = o0;
            *(float2*)&Out[base1] = o1;
        }
    }
}

// ---------------------------------------------------------------------------
// Launch
// ---------------------------------------------------------------------------
extern "C" void kernel_launch(void* const* d_in, const int* in_sizes, int n_in,
                              void* d_out, int out_size) {
    const float* x     = (const float*)d_in[0];
    const float* Wq    = (const float*)d_in[1];
    const float* bq    = (const float*)d_in[2];
    const float* Wk    = (const float*)d_in[3];
    const float* bk    = (const float*)d_in[4];
    const float* Wv    = (const float*)d_in[5];
    const float* bv    = (const float*)d_in[6];
    const float* gamma = (const float*)d_in[7];
    float* out = (float*)d_out;

    float *wt, *s;
    __nv_bfloat16 *qT, *kT, *v, *p;
    cudaGetSymbolAddress((void**)&wt, g_wt);
    cudaGetSymbolAddress((void**)&qT, g_qT);
    cudaGetSymbolAddress((void**)&kT, g_kT);
    cudaGetSymbolAddress((void**)&v,  g_v);
    cudaGetSymbolAddress((void**)&s,  g_s);
    cudaGetSymbolAddress((void**)&p,  g_p);

    // 1) W transposes (wt[w][c][d] = W[d][c])
    transpose_w<<<dim3((CC * CC) / 256, 3), 256>>>(Wq, Wk, Wv);

    // 2) qT/kT[b][token][d] = sum_c x[b][c][token] * wt[c][d] + b[d]  (bias on N)
    dim3 gQT(CC / 128, NN / 128, BB);
    gemm_tn_bf16<<<gQT, 256>>>(x, CN, wt + 0 * CC * CC, 0, qT, (long)NN * CC,
                               nullptr, bq, NN, CC, CC);
    gemm_tn_bf16<<<gQT, 256>>>(x, CN, wt + 1 * CC * CC, 0, kT, (long)NN * CC,
                               nullptr, bk, NN, CC, CC);

    // 3) v[b][d][n] = sum_c wt_v[c][d] * x[b][c][n] + bv[d]           (bias on M)
    dim3 gV(NN / 128, CC / 128, BB);
    gemm_tn_bf16<<<gV, 256>>>(wt + 2 * CC * CC, 0, x, CN, v, CN,
                              bv, nullptr, CC, NN, CC);

    // 4) scores: s[b][m][n] = (1/64) * kT[m]·qT[n]   (HMMA bf16, fp32 acc)
    score_hmma<<<dim3(NN / 128, NN / 128, BB), 256>>>(kT, qT, s);

    // 5) row softmax over n → bf16 probs
    softmax_rows<<<BB * NN, 256>>>(s, p);

    // 6) out[b][c][m] = gamma * v[c]·P[m] + x[b][c][m]   (HMMA bf16)
    out_hmma<<<dim3(NN / 128, CC / 128, BB), 256>>>(v, p, x, gamma, out);
}